// round 16
// baseline (speedup 1.0000x reference)
#include <cuda_runtime.h>
#include <cuda_fp16.h>

#define NN 100000
#define EE 1600000
#define CC 8
#define HH 64
#define BB 16
#define NFEAT 140
#define CFEAT 18
#define OPED 64
#define ALPHAC 0.2f
#define ROWS (CC*NN)

typedef unsigned long long ull;
typedef unsigned int uint;

// ---------------- device scratch ----------------
__device__ __half g_x  [(size_t)ROWS*HH];      // node states fp16, CONFIG-major [c][n][h]
__device__ uint4  g_xd4[2][(size_t)NN*64];     // x @ Wd fp16, NODE-major [n][c][h], ping-pong
__device__ float  g_xp [(size_t)ROWS*HH];      // layer-0 x @ Wp + bp, config-major (fp32)
__device__ int    g_rowptr[NN+1];
__device__ int    g_wptr[NN];
__device__ int    g_col[2*EE];
__device__ float  g_pooled[BB*CC*HH];

__device__ __forceinline__ float lrelu(float v){ return v > 0.f ? v : ALPHAC*v; }

__device__ __forceinline__ float warp_sum(float v){
  v += __shfl_xor_sync(0xffffffffu, v, 16);
  v += __shfl_xor_sync(0xffffffffu, v, 8);
  v += __shfl_xor_sync(0xffffffffu, v, 4);
  v += __shfl_xor_sync(0xffffffffu, v, 2);
  v += __shfl_xor_sync(0xffffffffu, v, 1);
  return v;
}

// ---- packed f32x2 helpers (layer0) ----
__device__ __forceinline__ ull f2_pack(float a, float b){
  ull r; asm("mov.b64 %0, {%1,%2};" : "=l"(r) : "f"(a), "f"(b)); return r;
}
__device__ __forceinline__ float2 f2_unpack(ull v){
  float2 r; asm("mov.b64 {%0,%1}, %2;" : "=f"(r.x), "=f"(r.y) : "l"(v)); return r;
}
__device__ __forceinline__ void fma2(ull &acc, ull a, ull b){
  asm("fma.rn.f32x2 %0, %1, %2, %0;" : "+l"(acc) : "l"(a), "l"(b));
}

// ---- mma.sync m16n8k16 row.col f32.f16.f16.f32 ----
__device__ __forceinline__ void mma16816(float&c0,float&c1,float&c2,float&c3,
                                         uint a0,uint a1,uint a2,uint a3,
                                         uint b0,uint b1){
  asm volatile("mma.sync.aligned.m16n8k16.row.col.f32.f16.f16.f32 "
    "{%0,%1,%2,%3},{%4,%5,%6,%7},{%8,%9},{%0,%1,%2,%3};"
    : "+f"(c0),"+f"(c1),"+f"(c2),"+f"(c3)
    : "r"(a0),"r"(a1),"r"(a2),"r"(a3),"r"(b0),"r"(b1));
}

// ---------------- grid barrier (persistent kernels, grid == 148) ----------------
__device__ unsigned g_barcnt = 0;
__device__ volatile unsigned g_bargen = 0;

__device__ __forceinline__ void grid_sync(){
  __syncthreads();
  if (threadIdx.x == 0){
    __threadfence();
    unsigned gen = g_bargen;
    if (atomicAdd(&g_barcnt, 1u) == gridDim.x - 1){
      g_barcnt = 0;
      __threadfence();
      g_bargen = gen + 1;
    } else {
      while (g_bargen == gen) __nanosleep(64);
    }
  }
  __syncthreads();
}

// ---------------- tiny zero kernel ----------------
__global__ void k_zero(){
  int i = blockIdx.x*blockDim.x + threadIdx.x;
  if (i < NN) g_wptr[i] = 0;
  if (i < BB*CC*HH) g_pooled[i] = 0.f;
}

// ---------------- CSR scan + fill ----------------
__global__ void k_csr_b(const int* __restrict__ src, const int* __restrict__ dst){
  __shared__ int ss[1024];
  if (blockIdx.x == 0){
    int t = threadIdx.x;
    const int CH = (NN + 1023) / 1024;
    int lo = t*CH;
    int hi = lo + CH; if (hi > NN) hi = NN;
    int s = 0;
    for (int i = lo; i < hi; i++) s += g_wptr[i];
    ss[t] = s;
    __syncthreads();
    for (int off = 1; off < 1024; off <<= 1) {
      int v = (t >= off) ? ss[t-off] : 0;
      __syncthreads();
      ss[t] += v;
      __syncthreads();
    }
    int run = (t == 0) ? 0 : ss[t-1];
    for (int i = lo; i < hi; i++) {
      int cv = g_wptr[i];
      g_rowptr[i] = run;
      g_wptr[i]   = run;
      run += cv;
    }
    if (t == 1023) g_rowptr[NN] = ss[1023];
  }
  grid_sync();
  int tid = blockIdx.x*blockDim.x + threadIdx.x;
  int nt  = gridDim.x*blockDim.x;
  for (int e = tid; e < EE; e += nt){
    int s = src[e], d = dst[e];
    int p = atomicAdd(&g_wptr[d], 1);  g_col[p] = s;
    int q = atomicAdd(&g_wptr[s], 1);  g_col[q] = d;
  }
}

// ---------------- layer 0: 8-node weight stream + fused edge count ----------------
#define L0W 4
__global__ void __launch_bounds__(128, 5)
k_layer0(const float* __restrict__ node_feats,
         const float* __restrict__ config_feats,
         const int*   __restrict__ op_ids,
         const float* __restrict__ op_emb,
         const float* __restrict__ Wd,
         const float* __restrict__ Wp,
         const float* __restrict__ bp,
         const int*   __restrict__ src,
         const int*   __restrict__ dst) {
  __shared__ float sBase[L0W][8*204];
  __shared__ float sCf[L0W][8*CC*CFEAT];
  int tid = threadIdx.x;

  {
    int t0 = blockIdx.x*blockDim.x + tid;
    int nt = gridDim.x*blockDim.x;
    for (int e = t0; e < EE; e += nt){
      atomicAdd(&g_wptr[dst[e]], 1);
      atomicAdd(&g_wptr[src[e]], 1);
    }
  }

  int w = tid >> 5, l = tid & 31;
  float* myBase = sBase[w];
  float* myCf   = sCf[w];
  int gw = (blockIdx.x*blockDim.x + tid) >> 5;
  int nw = (gridDim.x*blockDim.x) >> 5;
  const ull* Wd2 = (const ull*)Wd;
  const ull* Wp2 = (const ull*)Wp;
  ull bp2 = __ldg((const ull*)bp + l);

  const int NGR = NN / 8;
  for (int grp = gw; grp < NGR; grp += nw) {
    int n0 = grp * 8;
    #pragma unroll
    for (int r = 0; r < 8; r++) {
      int n = n0 + r;
      int oid = __ldg(op_ids + n);
      for (int d = l; d < 204; d += 32)
        myBase[r*204 + d] = (d < OPED) ? __ldg(op_emb + oid*OPED + d)
                                       : __ldg(node_feats + (size_t)n*NFEAT + (d - OPED));
    }
    for (int i = l; i < 8*CC*CFEAT; i += 32)
      myCf[i] = __ldg(config_feats + (size_t)n0*CC*CFEAT + i);
    __syncwarp();

    ull accD[8], accP[8];
    #pragma unroll
    for (int r = 0; r < 8; r++) { accD[r] = 0ull; accP[r] = bp2; }
    #pragma unroll 2
    for (int d = 0; d < 204; d++) {
      ull wdp = __ldg(Wd2 + d*32 + l);
      ull wpp = __ldg(Wp2 + d*32 + l);
      #pragma unroll
      for (int r = 0; r < 8; r++) {
        float b = myBase[r*204 + d];
        ull bb = f2_pack(b, b);
        fma2(accD[r], wdp, bb);
        fma2(accP[r], wpp, bb);
      }
    }

    #pragma unroll 1
    for (int r = 0; r < 8; r++) {
      int n = n0 + r;
      ull aD[CC], aP[CC];
      #pragma unroll
      for (int c = 0; c < CC; c++) { aD[c] = accD[r]; aP[c] = accP[r]; }
      #pragma unroll
      for (int j = 0; j < CFEAT; j++) {
        ull wdp = __ldg(Wd2 + (204+j)*32 + l);
        ull wpp = __ldg(Wp2 + (204+j)*32 + l);
        #pragma unroll
        for (int c = 0; c < CC; c++) {
          float f = myCf[r*CC*CFEAT + c*CFEAT + j];
          ull ff = f2_pack(f, f);
          fma2(aD[c], wdp, ff);
          fma2(aP[c], wpp, ff);
        }
      }
      #pragma unroll
      for (int c = 0; c < CC; c++) {
        float2 rd = f2_unpack(aD[c]);
        ((half2*)g_xd4[0])[(size_t)n*256 + c*32 + l] = __floats2half2_rn(rd.x, rd.y);
        ((float2*)g_xp)[((size_t)c*NN + n)*32 + l] = f2_unpack(aP[c]);
      }
    }
    __syncwarp();
  }
}

// ---------------- gather helpers ----------------
__device__ __forceinline__ void acc_tree8(const uint4& A, const uint4& B,
                                          const uint4& C, const uint4& D,
                                          const uint4& E, const uint4& F,
                                          const uint4& G, const uint4& H, float* f){
  const half2* x0 = (const half2*)&A; const half2* x1 = (const half2*)&B;
  const half2* x2 = (const half2*)&C; const half2* x3 = (const half2*)&D;
  const half2* x4 = (const half2*)&E; const half2* x5 = (const half2*)&F;
  const half2* x6 = (const half2*)&G; const half2* x7 = (const half2*)&H;
  #pragma unroll
  for (int k = 0; k < 4; k++){
    half2 s = __hadd2(__hadd2(__hadd2(x0[k], x1[k]), __hadd2(x2[k], x3[k])),
                      __hadd2(__hadd2(x4[k], x5[k]), __hadd2(x6[k], x7[k])));
    float2 v = __half22float2(s);
    f[2*k]   += v.x;
    f[2*k+1] += v.y;
  }
}
__device__ __forceinline__ void acc_tree4(const uint4& A, const uint4& B,
                                          const uint4& C, const uint4& D, float* f){
  const half2* x0 = (const half2*)&A; const half2* x1 = (const half2*)&B;
  const half2* x2 = (const half2*)&C; const half2* x3 = (const half2*)&D;
  #pragma unroll
  for (int k = 0; k < 4; k++){
    half2 s = __hadd2(__hadd2(x0[k], x1[k]), __hadd2(x2[k], x3[k]));
    float2 v = __half22float2(s);
    f[2*k]   += v.x;
    f[2*k+1] += v.y;
  }
}
__device__ __forceinline__ void acc_one(const uint4& A, float* f){
  const half2* x = (const half2*)&A;
  #pragma unroll
  for (int k = 0; k < 4; k++){
    float2 v = __half22float2(x[k]);
    f[2*k]   += v.x;
    f[2*k+1] += v.y;
  }
}

__device__ __forceinline__ void gather_node(int n, int coff, const uint4* __restrict__ xsrc,
                                            float* __restrict__ syrow, int lane, int cfg_local){
  int beg = g_rowptr[n], end = g_rowptr[n+1];
  float f[8];
  #pragma unroll
  for (int i = 0; i < 8; i++) f[i] = 0.f;
  int e = beg;
  for (; e + 8 <= end; e += 8) {
    int s0 = __ldg(g_col + e);     int s1 = __ldg(g_col + e + 1);
    int s2 = __ldg(g_col + e + 2); int s3 = __ldg(g_col + e + 3);
    int s4 = __ldg(g_col + e + 4); int s5 = __ldg(g_col + e + 5);
    int s6 = __ldg(g_col + e + 6); int s7 = __ldg(g_col + e + 7);
    uint4 a0 = __ldg(xsrc + (size_t)s0*64 + coff);
    uint4 a1 = __ldg(xsrc + (size_t)s1*64 + coff);
    uint4 a2 = __ldg(xsrc + (size_t)s2*64 + coff);
    uint4 a3 = __ldg(xsrc + (size_t)s3*64 + coff);
    uint4 a4 = __ldg(xsrc + (size_t)s4*64 + coff);
    uint4 a5 = __ldg(xsrc + (size_t)s5*64 + coff);
    uint4 a6 = __ldg(xsrc + (size_t)s6*64 + coff);
    uint4 a7 = __ldg(xsrc + (size_t)s7*64 + coff);
    acc_tree8(a0, a1, a2, a3, a4, a5, a6, a7, f);
  }
  for (; e + 4 <= end; e += 4) {
    int s0 = __ldg(g_col + e);     int s1 = __ldg(g_col + e + 1);
    int s2 = __ldg(g_col + e + 2); int s3 = __ldg(g_col + e + 3);
    uint4 a0 = __ldg(xsrc + (size_t)s0*64 + coff);
    uint4 a1 = __ldg(xsrc + (size_t)s1*64 + coff);
    uint4 a2 = __ldg(xsrc + (size_t)s2*64 + coff);
    uint4 a3 = __ldg(xsrc + (size_t)s3*64 + coff);
    acc_tree4(a0, a1, a2, a3, f);
  }
  for (; e < end; e++) {
    int s = __ldg(g_col + e);
    uint4 A = __ldg(xsrc + (size_t)s*64 + coff);
    acc_one(A, f);
  }
  float4* yo = (float4*)&syrow[cfg_local*64 + (lane&7)*8];
  yo[0] = make_float4(f[0], f[1], f[2], f[3]);
  yo[1] = make_float4(f[4], f[5], f[6], f[7]);
}

// ---------------- fused layer: gather + HMMA matvecs, W split hi/lo ----------------
// Warp = 4 nodes x 4 configs = 16 MMA rows. Row gid <-> node n0+(gid>>2), cfg CH*4+(gid&3).
// dyn smem: sy (8w x 1024 f32, 32KB) | sWp hi/lo (8+8KB) | sWd hi/lo (8+8KB) = 64KB
#define FSMEM 65536
template<int LAYER, int SRC, int DST, int CH>
__global__ void __launch_bounds__(256, 3)
k_fused(const float* __restrict__ Wp, const float* __restrict__ bp,
        const float* __restrict__ bd, const float* __restrict__ Wdn) {
  extern __shared__ __align__(16) char dsm[];
  float* sy   = (float*)dsm;                  // 32768 B
  half*  sWph = (half*)(dsm + 32768);         //  8192 B
  half*  sWpl = (half*)(dsm + 40960);         //  8192 B
  half*  sWdh = (half*)(dsm + 49152);         //  8192 B
  half*  sWdl = (half*)(dsm + 57344);         //  8192 B

  int tid = threadIdx.x;
  int w = tid >> 5, lane = tid & 31;
  int gid = lane >> 2, t4 = lane & 3;

  // stage weights transposed, split hi/lo fp16: Wt[n][k] = W[k][n]
  if (LAYER > 0)
    for (int i = tid; i < 4096; i += 256){
      int n = i >> 6, k = i & 63;
      float wv = __ldg(Wp + k*64 + n);
      half hi = __float2half_rn(wv);
      sWph[i] = hi;
      sWpl[i] = __float2half_rn(wv - __half2float(hi));
    }
  if (LAYER < 2)
    for (int i = tid; i < 4096; i += 256){
      int n = i >> 6, k = i & 63;
      float wv = __ldg(Wdn + k*64 + n);
      half hi = __float2half_rn(wv);
      sWdh[i] = hi;
      sWdl[i] = __float2half_rn(wv - __half2float(hi));
    }
  __syncthreads();

  float* syw = sy + w*1024;
  const uint* wph = (const uint*)sWph;
  const uint* wpl = (const uint*)sWpl;
  const uint* wdh = (const uint*)sWdh;
  const uint* wdl = (const uint*)sWdl;

  const int cfg_local = lane >> 3;
  const int coff = (CH*4 + cfg_local)*8 + (lane & 7);

  int gwarp = (blockIdx.x*blockDim.x + tid) >> 5;
  int nwarp = (gridDim.x*blockDim.x) >> 5;
  const uint4* xsrc = g_xd4[SRC];
  half2* gxo = (half2*)g_x;

  for (int n0 = 4*gwarp; n0 < NN; n0 += 4*nwarp) {
    // ---- phase 1: gather 4 nodes x 4 configs into sy ----
    #pragma unroll
    for (int r = 0; r < 4; r++)
      gather_node(n0 + r, coff, xsrc, syw + r*256, lane, cfg_local);
    __syncwarp();

    int n_lo = n0 + (gid >> 2);
    int n_hi = n_lo + 2;
    int cg   = CH*4 + (gid & 3);

    // ---- Wp MMA (A loaded straight from g_x) or xp load ----
    float cx0[8], cx1[8], cx2[8], cx3[8];
    if (LAYER > 0) {
      const uint* gxu = (const uint*)g_x;
      uint afr[4][4];
      #pragma unroll
      for (int kt = 0; kt < 4; kt++){
        afr[kt][0] = __ldg(gxu + ((size_t)cg*NN + n_lo)*32 + kt*8 + t4);
        afr[kt][1] = __ldg(gxu + ((size_t)cg*NN + n_hi)*32 + kt*8 + t4);
        afr[kt][2] = __ldg(gxu + ((size_t)cg*NN + n_lo)*32 + kt*8 + t4 + 4);
        afr[kt][3] = __ldg(gxu + ((size_t)cg*NN + n_hi)*32 + kt*8 + t4 + 4);
      }
      #pragma unroll
      for (int nt = 0; nt < 8; nt++){
        float2 bpv = __ldg((const float2*)(bp + nt*8 + t4*2));
        float c0 = bpv.x, c1 = bpv.y, c2 = bpv.x, c3 = bpv.y;
        #pragma unroll
        for (int kt = 0; kt < 4; kt++){
          uint bh0 = wph[(nt*8+gid)*32 + kt*8 + t4];
          uint bh1 = wph[(nt*8+gid)*32 + kt*8 + t4 + 4];
          uint bl0 = wpl[(nt*8+gid)*32 + kt*8 + t4];
          uint bl1 = wpl[(nt*8+gid)*32 + kt*8 + t4 + 4];
          mma16816(c0, c1, c2, c3, afr[kt][0], afr[kt][1], afr[kt][2], afr[kt][3], bh0, bh1);
          mma16816(c0, c1, c2, c3, afr[kt][0], afr[kt][1], afr[kt][2], afr[kt][3], bl0, bl1);
        }
        cx0[nt] = c0; cx1[nt] = c1; cx2[nt] = c2; cx3[nt] = c3;
      }
    } else {
      const float2* xp2 = (const float2*)g_xp;
      #pragma unroll
      for (int nt = 0; nt < 8; nt++){
        float2 lo = __ldg(xp2 + ((size_t)cg*NN + n_lo)*32 + nt*4 + t4);
        float2 hi = __ldg(xp2 + ((size_t)cg*NN + n_hi)*32 + nt*4 + t4);
        cx0[nt] = lo.x; cx1[nt] = lo.y; cx2[nt] = hi.x; cx3[nt] = hi.y;
      }
    }

    // ---- residual + l2norm (fp32 stash, single rounding) ----
    float ssl = 0.f, ssh = 0.f;
    #pragma unroll
    for (int nt = 0; nt < 8; nt++){
      float2 bdv = __ldg((const float2*)(bd + nt*8 + t4*2));
      float2 ylo = *(const float2*)(syw + (gid>>2)*256     + (gid&3)*64 + nt*8 + t4*2);
      float2 yhi = *(const float2*)(syw + ((gid>>2)+2)*256 + (gid&3)*64 + nt*8 + t4*2);
      cx0[nt] += lrelu(ylo.x + bdv.x);
      cx1[nt] += lrelu(ylo.y + bdv.y);
      cx2[nt] += lrelu(yhi.x + bdv.x);
      cx3[nt] += lrelu(yhi.y + bdv.y);
      ssl += cx0[nt]*cx0[nt] + cx1[nt]*cx1[nt];
      ssh += cx2[nt]*cx2[nt] + cx3[nt]*cx3[nt];
    }
    ssl += __shfl_xor_sync(0xffffffffu, ssl, 1);
    ssl += __shfl_xor_sync(0xffffffffu, ssl, 2);
    ssh += __shfl_xor_sync(0xffffffffu, ssh, 1);
    ssh += __shfl_xor_sync(0xffffffffu, ssh, 2);
    float rl = rsqrtf(fmaxf(ssl, 1e-12f));
    float rh = rsqrtf(fmaxf(ssh, 1e-12f));

    uint alo[8], ahi[8];   // fp16 x' pairs — ALSO the A frags for the Wd MMA
    #pragma unroll
    for (int nt = 0; nt < 8; nt++){
      half2 vlo = __floats2half2_rn(cx0[nt]*rl, cx1[nt]*rl);
      half2 vhi = __floats2half2_rn(cx2[nt]*rh, cx3[nt]*rh);
      gxo[((size_t)cg*NN + n_lo)*32 + nt*4 + t4] = vlo;
      gxo[((size_t)cg*NN + n_hi)*32 + nt*4 + t4] = vhi;
      alo[nt] = *(uint*)&vlo;
      ahi[nt] = *(uint*)&vhi;
    }

    // ---- Wd MMA: xd_next = x' @ Wd (A frags = stash registers) ----
    if (LAYER < 2) {
      half2* xdo = (half2*)g_xd4[DST];
      #pragma unroll
      for (int nt = 0; nt < 8; nt++){
        float c0 = 0.f, c1 = 0.f, c2 = 0.f, c3 = 0.f;
        #pragma unroll
        for (int kt = 0; kt < 4; kt++){
          uint a0 = alo[2*kt], a1 = ahi[2*kt], a2 = alo[2*kt+1], a3 = ahi[2*kt+1];
          uint bh0 = wdh[(nt*8+gid)*32 + kt*8 + t4];
          uint bh1 = wdh[(nt*8+gid)*32 + kt*8 + t4 + 4];
          uint bl0 = wdl[(nt*8+gid)*32 + kt*8 + t4];
          uint bl1 = wdl[(nt*8+gid)*32 + kt*8 + t4 + 4];
          mma16816(c0, c1, c2, c3, a0, a1, a2, a3, bh0, bh1);
          mma16816(c0, c1, c2, c3, a0, a1, a2, a3, bl0, bl1);
        }
        xdo[(size_t)n_lo*256 + cg*32 + nt*4 + t4] = __floats2half2_rn(c0, c1);
        xdo[(size_t)n_hi*256 + cg*32 + nt*4 + t4] = __floats2half2_rn(c2, c3);
      }
    }
    __syncwarp();
  }
}

// ---------------- pooling (fp16 g_x) ----------------
#define PCHUNK 64
#define NCHUNKS ((NN + PCHUNK - 1) / PCHUNK)
__global__ void k_pool(const int* __restrict__ gid) {
  int gw   = (blockIdx.x*blockDim.x + threadIdx.x) >> 5;
  int lane = threadIdx.x & 31;
  int nw   = (gridDim.x*blockDim.x) >> 5;
  const int TOT = NCHUNKS * CC;
  for (int w = gw; w < TOT; w += nw) {
    int c  = w / NCHUNKS;
    int ch = w - c*NCHUNKS;
    int n0 = ch * PCHUNK;
    int n1 = n0 + PCHUNK; if (n1 > NN) n1 = NN;
    const half2* xs = (const half2*)g_x + ((size_t)c*NN)*32;
    float p0 = 0.f, p1 = 0.f;
    int curg = __ldg(gid + n0);
    for (int n = n0; n < n1; n += 4) {
      int4 g4 = __ldg((const int4*)(gid + n));
      float2 v0 = __half22float2(xs[(size_t)(n  )*32 + lane]);
      float2 v1 = __half22float2(xs[(size_t)(n+1)*32 + lane]);
      float2 v2 = __half22float2(xs[(size_t)(n+2)*32 + lane]);
      float2 v3 = __half22float2(xs[(size_t)(n+3)*32 + lane]);
      int gg[4] = {g4.x, g4.y, g4.z, g4.w};
      float vx[4] = {v0.x, v1.x, v2.x, v3.x};
      float vy[4] = {v0.y, v1.y, v2.y, v3.y};
      #pragma unroll
      for (int k = 0; k < 4; k++) {
        if (gg[k] != curg) {
          atomicAdd(&g_pooled[((size_t)curg*CC + c)*HH + 2*lane    ], p0);
          atomicAdd(&g_pooled[((size_t)curg*CC + c)*HH + 2*lane + 1], p1);
          p0 = 0.f; p1 = 0.f; curg = gg[k];
        }
        p0 += vx[k]; p1 += vy[k];
      }
    }
    atomicAdd(&g_pooled[((size_t)curg*CC + c)*HH + 2*lane    ], p0);
    atomicAdd(&g_pooled[((size_t)curg*CC + c)*HH + 2*lane + 1], p1);
  }
}

// ---------------- final MLP ----------------
__global__ void k_mlp(const float* __restrict__ Wm0, const float* __restrict__ bm0,
                      const float* __restrict__ Wm1, const float* __restrict__ bm1,
                      const float* __restrict__ Wm2, const float* __restrict__ bm2,
                      float* __restrict__ out) {
  __shared__ float s_in[HH], s_h[HH], rr[HH];
  int bc = blockIdx.x;
  int h = threadIdx.x;
  s_in[h] = g_pooled[(size_t)bc*HH + h];
  __syncthreads();
  float a = __ldg(bm0 + h);
  #pragma unroll 8
  for (int d = 0; d < HH; d++) a += s_in[d] * __ldg(Wm0 + d*HH + h);
  a = lrelu(a);
  s_h[h] = a;
  __syncthreads();
  float a2 = __ldg(bm1 + h);
  #pragma unroll 8
  for (int d = 0; d < HH; d++) a2 += s_h[d] * __ldg(Wm1 + d*HH + h);
  a2 = lrelu(a2);
  rr[h] = a2 * __ldg(Wm2 + h);
  __syncthreads();
  if (h < 32) {
    float v = rr[h] + rr[h+32];
    v = warp_sum(v);
    if (h == 0) out[bc] = v + __ldg(bm2);
  }
}

// ---------------- host orchestration ----------------
extern "C" void kernel_launch(void* const* d_in, const int* in_sizes, int n_in,
                              void* d_out, int out_size) {
  (void)in_sizes; (void)n_in; (void)out_size;
  const float* node_feats   = (const float*)d_in[0];
  const float* config_feats = (const float*)d_in[1];
  const int*   op_ids       = (const int*)  d_in[2];
  const int*   src          = (const int*)  d_in[3];
  const int*   dst          = (const int*)  d_in[4];
  const int*   graph_ids    = (const int*)  d_in[5];
  const float* op_emb       = (const float*)d_in[6];
  const float* W_d0 = (const float*)d_in[7];  const float* b_d0 = (const float*)d_in[8];
  const float* W_p0 = (const float*)d_in[9];  const float* b_p0 = (const float*)d_in[10];
  const float* W_d1 = (const float*)d_in[11]; const float* b_d1 = (const float*)d_in[12];
  const float* W_p1 = (const float*)d_in[13]; const float* b_p1 = (const float*)d_in[14];
  const float* W_d2 = (const float*)d_in[15]; const float* b_d2 = (const float*)d_in[16];
  const float* W_p2 = (const float*)d_in[17]; const float* b_p2 = (const float*)d_in[18];
  const float* W_m0 = (const float*)d_in[19]; const float* b_m0 = (const float*)d_in[20];
  const float* W_m1 = (const float*)d_in[21]; const float* b_m1 = (const float*)d_in[22];
  const float* W_m2 = (const float*)d_in[23]; const float* b_m2 = (const float*)d_in[24];
  float* out = (float*)d_out;

  cudaFuncSetAttribute(k_fused<0,0,1,0>, cudaFuncAttributeMaxDynamicSharedMemorySize, FSMEM);
  cudaFuncSetAttribute(k_fused<0,0,1,1>, cudaFuncAttributeMaxDynamicSharedMemorySize, FSMEM);
  cudaFuncSetAttribute(k_fused<1,1,0,0>, cudaFuncAttributeMaxDynamicSharedMemorySize, FSMEM);
  cudaFuncSetAttribute(k_fused<1,1,0,1>, cudaFuncAttributeMaxDynamicSharedMemorySize, FSMEM);
  cudaFuncSetAttribute(k_fused<2,0,0,0>, cudaFuncAttributeMaxDynamicSharedMemorySize, FSMEM);
  cudaFuncSetAttribute(k_fused<2,0,0,1>, cudaFuncAttributeMaxDynamicSharedMemorySize, FSMEM);

  k_zero<<<(NN+255)/256, 256>>>();
  k_layer0<<<1024, 128>>>(node_feats, config_feats, op_ids, op_emb,
                          W_d0, W_p0, b_p0, src, dst);
  k_csr_b<<<148, 1024>>>(src, dst);

  // launch 4 (ncu-captured): fused layer 0, config half 0
  k_fused<0,0,1,0><<<1024, 256, FSMEM>>>(nullptr, nullptr, b_d0, W_d1);
  k_fused<0,0,1,1><<<1024, 256, FSMEM>>>(nullptr, nullptr, b_d0, W_d1);
  k_fused<1,1,0,0><<<1024, 256, FSMEM>>>(W_p1, b_p1, b_d1, W_d2);
  k_fused<1,1,0,1><<<1024, 256, FSMEM>>>(W_p1, b_p1, b_d1, W_d2);
  k_fused<2,0,0,0><<<1024, 256, FSMEM>>>(W_p2, b_p2, b_d2, nullptr);
  k_fused<2,0,0,1><<<1024, 256, FSMEM>>>(W_p2, b_p2, b_d2, nullptr);

  k_pool<<<1024, 256>>>(graph_ids);
  k_mlp<<<BB*CC, HH>>>(W_m0, b_m0, W_m1, b_m1, W_m2, b_m2, out);
}

// round 17
// speedup vs baseline: 1.0435x; 1.0435x over previous
#include <cuda_runtime.h>
#include <cuda_fp16.h>

#define NN 100000
#define EE 1600000
#define CC 8
#define HH 64
#define BB 16
#define NFEAT 140
#define CFEAT 18
#define OPED 64
#define ALPHAC 0.2f
#define ROWS (CC*NN)

typedef unsigned long long ull;
typedef unsigned int uint;

// ---------------- device scratch ----------------
__device__ __half g_x  [(size_t)ROWS*HH];      // node states fp16, CONFIG-major [c][n][h]
__device__ uint4  g_xd4[2][(size_t)NN*64];     // x @ Wd fp16, NODE-major [n][c][h], ping-pong
__device__ float  g_xp [(size_t)ROWS*HH];      // layer-0 x @ Wp + bp, config-major (fp32)
__device__ int    g_rowptr[NN+1];
__device__ int    g_wptr[NN];
__device__ int    g_col[2*EE];
__device__ float  g_pooled[BB*CC*HH];

__device__ __forceinline__ float lrelu(float v){ return v > 0.f ? v : ALPHAC*v; }

__device__ __forceinline__ float warp_sum(float v){
  v += __shfl_xor_sync(0xffffffffu, v, 16);
  v += __shfl_xor_sync(0xffffffffu, v, 8);
  v += __shfl_xor_sync(0xffffffffu, v, 4);
  v += __shfl_xor_sync(0xffffffffu, v, 2);
  v += __shfl_xor_sync(0xffffffffu, v, 1);
  return v;
}

// ---- packed f32x2 helpers (layer0) ----
__device__ __forceinline__ ull f2_pack(float a, float b){
  ull r; asm("mov.b64 %0, {%1,%2};" : "=l"(r) : "f"(a), "f"(b)); return r;
}
__device__ __forceinline__ float2 f2_unpack(ull v){
  float2 r; asm("mov.b64 {%0,%1}, %2;" : "=f"(r.x), "=f"(r.y) : "l"(v)); return r;
}
__device__ __forceinline__ void fma2(ull &acc, ull a, ull b){
  asm("fma.rn.f32x2 %0, %1, %2, %0;" : "+l"(acc) : "l"(a), "l"(b));
}

// ---- mma.sync m16n8k16 row.col f32.f16.f16.f32 ----
__device__ __forceinline__ void mma16816(float&c0,float&c1,float&c2,float&c3,
                                         uint a0,uint a1,uint a2,uint a3,
                                         uint b0,uint b1){
  asm volatile("mma.sync.aligned.m16n8k16.row.col.f32.f16.f16.f32 "
    "{%0,%1,%2,%3},{%4,%5,%6,%7},{%8,%9},{%0,%1,%2,%3};"
    : "+f"(c0),"+f"(c1),"+f"(c2),"+f"(c3)
    : "r"(a0),"r"(a1),"r"(a2),"r"(a3),"r"(b0),"r"(b1));
}

// ---------------- grid barrier (persistent kernels, grid == 148) ----------------
__device__ unsigned g_barcnt = 0;
__device__ volatile unsigned g_bargen = 0;

__device__ __forceinline__ void grid_sync(){
  __syncthreads();
  if (threadIdx.x == 0){
    __threadfence();
    unsigned gen = g_bargen;
    if (atomicAdd(&g_barcnt, 1u) == gridDim.x - 1){
      g_barcnt = 0;
      __threadfence();
      g_bargen = gen + 1;
    } else {
      while (g_bargen == gen) __nanosleep(64);
    }
  }
  __syncthreads();
}

// ---------------- tiny zero kernel ----------------
__global__ void k_zero(){
  int i = blockIdx.x*blockDim.x + threadIdx.x;
  if (i < NN) g_wptr[i] = 0;
  if (i < BB*CC*HH) g_pooled[i] = 0.f;
}

// ---------------- CSR scan + fill ----------------
__global__ void k_csr_b(const int* __restrict__ src, const int* __restrict__ dst){
  __shared__ int ss[1024];
  if (blockIdx.x == 0){
    int t = threadIdx.x;
    const int CH = (NN + 1023) / 1024;
    int lo = t*CH;
    int hi = lo + CH; if (hi > NN) hi = NN;
    int s = 0;
    for (int i = lo; i < hi; i++) s += g_wptr[i];
    ss[t] = s;
    __syncthreads();
    for (int off = 1; off < 1024; off <<= 1) {
      int v = (t >= off) ? ss[t-off] : 0;
      __syncthreads();
      ss[t] += v;
      __syncthreads();
    }
    int run = (t == 0) ? 0 : ss[t-1];
    for (int i = lo; i < hi; i++) {
      int cv = g_wptr[i];
      g_rowptr[i] = run;
      g_wptr[i]   = run;
      run += cv;
    }
    if (t == 1023) g_rowptr[NN] = ss[1023];
  }
  grid_sync();
  int tid = blockIdx.x*blockDim.x + threadIdx.x;
  int nt  = gridDim.x*blockDim.x;
  for (int e = tid; e < EE; e += nt){
    int s = src[e], d = dst[e];
    int p = atomicAdd(&g_wptr[d], 1);  g_col[p] = s;
    int q = atomicAdd(&g_wptr[s], 1);  g_col[q] = d;
  }
}

// ---------------- layer 0: 8-node weight stream + fused edge count ----------------
#define L0W 4
__global__ void __launch_bounds__(128, 5)
k_layer0(const float* __restrict__ node_feats,
         const float* __restrict__ config_feats,
         const int*   __restrict__ op_ids,
         const float* __restrict__ op_emb,
         const float* __restrict__ Wd,
         const float* __restrict__ Wp,
         const float* __restrict__ bp,
         const int*   __restrict__ src,
         const int*   __restrict__ dst) {
  __shared__ float sBase[L0W][8*204];
  __shared__ float sCf[L0W][8*CC*CFEAT];
  int tid = threadIdx.x;

  {
    int t0 = blockIdx.x*blockDim.x + tid;
    int nt = gridDim.x*blockDim.x;
    for (int e = t0; e < EE; e += nt){
      atomicAdd(&g_wptr[dst[e]], 1);
      atomicAdd(&g_wptr[src[e]], 1);
    }
  }

  int w = tid >> 5, l = tid & 31;
  float* myBase = sBase[w];
  float* myCf   = sCf[w];
  int gw = (blockIdx.x*blockDim.x + tid) >> 5;
  int nw = (gridDim.x*blockDim.x) >> 5;
  const ull* Wd2 = (const ull*)Wd;
  const ull* Wp2 = (const ull*)Wp;
  ull bp2 = __ldg((const ull*)bp + l);

  const int NGR = NN / 8;
  for (int grp = gw; grp < NGR; grp += nw) {
    int n0 = grp * 8;
    #pragma unroll
    for (int r = 0; r < 8; r++) {
      int n = n0 + r;
      int oid = __ldg(op_ids + n);
      for (int d = l; d < 204; d += 32)
        myBase[r*204 + d] = (d < OPED) ? __ldg(op_emb + oid*OPED + d)
                                       : __ldg(node_feats + (size_t)n*NFEAT + (d - OPED));
    }
    for (int i = l; i < 8*CC*CFEAT; i += 32)
      myCf[i] = __ldg(config_feats + (size_t)n0*CC*CFEAT + i);
    __syncwarp();

    ull accD[8], accP[8];
    #pragma unroll
    for (int r = 0; r < 8; r++) { accD[r] = 0ull; accP[r] = bp2; }
    #pragma unroll 2
    for (int d = 0; d < 204; d++) {
      ull wdp = __ldg(Wd2 + d*32 + l);
      ull wpp = __ldg(Wp2 + d*32 + l);
      #pragma unroll
      for (int r = 0; r < 8; r++) {
        float b = myBase[r*204 + d];
        ull bb = f2_pack(b, b);
        fma2(accD[r], wdp, bb);
        fma2(accP[r], wpp, bb);
      }
    }

    #pragma unroll 1
    for (int r = 0; r < 8; r++) {
      int n = n0 + r;
      ull aD[CC], aP[CC];
      #pragma unroll
      for (int c = 0; c < CC; c++) { aD[c] = accD[r]; aP[c] = accP[r]; }
      #pragma unroll
      for (int j = 0; j < CFEAT; j++) {
        ull wdp = __ldg(Wd2 + (204+j)*32 + l);
        ull wpp = __ldg(Wp2 + (204+j)*32 + l);
        #pragma unroll
        for (int c = 0; c < CC; c++) {
          float f = myCf[r*CC*CFEAT + c*CFEAT + j];
          ull ff = f2_pack(f, f);
          fma2(aD[c], wdp, ff);
          fma2(aP[c], wpp, ff);
        }
      }
      #pragma unroll
      for (int c = 0; c < CC; c++) {
        float2 rd = f2_unpack(aD[c]);
        ((half2*)g_xd4[0])[(size_t)n*256 + c*32 + l] = __floats2half2_rn(rd.x, rd.y);
        ((float2*)g_xp)[((size_t)c*NN + n)*32 + l] = f2_unpack(aP[c]);
      }
    }
    __syncwarp();
  }
}

// ---------------- gather helpers ----------------
__device__ __forceinline__ void acc_tree8(const uint4& A, const uint4& B,
                                          const uint4& C, const uint4& D,
                                          const uint4& E, const uint4& F,
                                          const uint4& G, const uint4& H, float* f){
  const half2* x0 = (const half2*)&A; const half2* x1 = (const half2*)&B;
  const half2* x2 = (const half2*)&C; const half2* x3 = (const half2*)&D;
  const half2* x4 = (const half2*)&E; const half2* x5 = (const half2*)&F;
  const half2* x6 = (const half2*)&G; const half2* x7 = (const half2*)&H;
  #pragma unroll
  for (int k = 0; k < 4; k++){
    half2 s = __hadd2(__hadd2(__hadd2(x0[k], x1[k]), __hadd2(x2[k], x3[k])),
                      __hadd2(__hadd2(x4[k], x5[k]), __hadd2(x6[k], x7[k])));
    float2 v = __half22float2(s);
    f[2*k]   += v.x;
    f[2*k+1] += v.y;
  }
}
__device__ __forceinline__ void acc_tree4(const uint4& A, const uint4& B,
                                          const uint4& C, const uint4& D, float* f){
  const half2* x0 = (const half2*)&A; const half2* x1 = (const half2*)&B;
  const half2* x2 = (const half2*)&C; const half2* x3 = (const half2*)&D;
  #pragma unroll
  for (int k = 0; k < 4; k++){
    half2 s = __hadd2(__hadd2(x0[k], x1[k]), __hadd2(x2[k], x3[k]));
    float2 v = __half22float2(s);
    f[2*k]   += v.x;
    f[2*k+1] += v.y;
  }
}
__device__ __forceinline__ void acc_one(const uint4& A, float* f){
  const half2* x = (const half2*)&A;
  #pragma unroll
  for (int k = 0; k < 4; k++){
    float2 v = __half22float2(x[k]);
    f[2*k]   += v.x;
    f[2*k+1] += v.y;
  }
}

// gather 4 configs of node n; write fp16 y into syrow (128 half2 per node slot)
__device__ __forceinline__ void gather_node(int n, int coff, const uint4* __restrict__ xsrc,
                                            half2* __restrict__ syrow, int lane, int cfg_local){
  int beg = g_rowptr[n], end = g_rowptr[n+1];
  float f[8];
  #pragma unroll
  for (int i = 0; i < 8; i++) f[i] = 0.f;
  int e = beg;
  for (; e + 8 <= end; e += 8) {
    int s0 = __ldg(g_col + e);     int s1 = __ldg(g_col + e + 1);
    int s2 = __ldg(g_col + e + 2); int s3 = __ldg(g_col + e + 3);
    int s4 = __ldg(g_col + e + 4); int s5 = __ldg(g_col + e + 5);
    int s6 = __ldg(g_col + e + 6); int s7 = __ldg(g_col + e + 7);
    uint4 a0 = __ldg(xsrc + (size_t)s0*64 + coff);
    uint4 a1 = __ldg(xsrc + (size_t)s1*64 + coff);
    uint4 a2 = __ldg(xsrc + (size_t)s2*64 + coff);
    uint4 a3 = __ldg(xsrc + (size_t)s3*64 + coff);
    uint4 a4 = __ldg(xsrc + (size_t)s4*64 + coff);
    uint4 a5 = __ldg(xsrc + (size_t)s5*64 + coff);
    uint4 a6 = __ldg(xsrc + (size_t)s6*64 + coff);
    uint4 a7 = __ldg(xsrc + (size_t)s7*64 + coff);
    acc_tree8(a0, a1, a2, a3, a4, a5, a6, a7, f);
  }
  for (; e + 4 <= end; e += 4) {
    int s0 = __ldg(g_col + e);     int s1 = __ldg(g_col + e + 1);
    int s2 = __ldg(g_col + e + 2); int s3 = __ldg(g_col + e + 3);
    uint4 a0 = __ldg(xsrc + (size_t)s0*64 + coff);
    uint4 a1 = __ldg(xsrc + (size_t)s1*64 + coff);
    uint4 a2 = __ldg(xsrc + (size_t)s2*64 + coff);
    uint4 a3 = __ldg(xsrc + (size_t)s3*64 + coff);
    acc_tree4(a0, a1, a2, a3, f);
  }
  for (; e < end; e++) {
    int s = __ldg(g_col + e);
    uint4 A = __ldg(xsrc + (size_t)s*64 + coff);
    acc_one(A, f);
  }
  // pack 8 floats -> 4 half2 -> one STS.64
  half2 h0 = __floats2half2_rn(f[0], f[1]);
  half2 h1 = __floats2half2_rn(f[2], f[3]);
  half2 h2 = __floats2half2_rn(f[4], f[5]);
  half2 h3 = __floats2half2_rn(f[6], f[7]);
  uint2* yo = (uint2*)&syrow[cfg_local*32 + (lane&7)*4];
  yo[0] = make_uint2((*(uint*)&h0), (*(uint*)&h1));
  yo[1] = make_uint2((*(uint*)&h2), (*(uint*)&h3));
}

// ---------------- fused layer: gather + HMMA matvecs, W split hi/lo, fp16 sy ----------------
// Warp = 4 nodes x 4 configs = 16 MMA rows. Row gid <-> node n0+(gid>>2), cfg CH*4+(gid&3).
// dyn smem: sy fp16 (8w x 512 half2, 16KB) | sWp hi/lo (16KB) | sWd hi/lo (16KB) = 48KB
#define FSMEM 49152
template<int LAYER, int SRC, int DST, int CH>
__global__ void __launch_bounds__(256, 4)
k_fused(const float* __restrict__ Wp, const float* __restrict__ bp,
        const float* __restrict__ bd, const float* __restrict__ Wdn) {
  extern __shared__ __align__(16) char dsm[];
  half2* sy   = (half2*)dsm;                  // 16384 B
  half*  sWph = (half*)(dsm + 16384);         //  8192 B
  half*  sWpl = (half*)(dsm + 24576);         //  8192 B
  half*  sWdh = (half*)(dsm + 32768);         //  8192 B
  half*  sWdl = (half*)(dsm + 40960);         //  8192 B

  int tid = threadIdx.x;
  int w = tid >> 5, lane = tid & 31;
  int gid = lane >> 2, t4 = lane & 3;

  if (LAYER > 0)
    for (int i = tid; i < 4096; i += 256){
      int n = i >> 6, k = i & 63;
      float wv = __ldg(Wp + k*64 + n);
      half hi = __float2half_rn(wv);
      sWph[i] = hi;
      sWpl[i] = __float2half_rn(wv - __half2float(hi));
    }
  if (LAYER < 2)
    for (int i = tid; i < 4096; i += 256){
      int n = i >> 6, k = i & 63;
      float wv = __ldg(Wdn + k*64 + n);
      half hi = __float2half_rn(wv);
      sWdh[i] = hi;
      sWdl[i] = __float2half_rn(wv - __half2float(hi));
    }
  __syncthreads();

  half2* syw = sy + w*512;      // 4 nodes x 128 half2
  const uint* wph = (const uint*)sWph;
  const uint* wpl = (const uint*)sWpl;
  const uint* wdh = (const uint*)sWdh;
  const uint* wdl = (const uint*)sWdl;

  const int cfg_local = lane >> 3;
  const int coff = (CH*4 + cfg_local)*8 + (lane & 7);

  int gwarp = (blockIdx.x*blockDim.x + tid) >> 5;
  int nwarp = (gridDim.x*blockDim.x) >> 5;
  const uint4* xsrc = g_xd4[SRC];
  half2* gxo = (half2*)g_x;

  for (int n0 = 4*gwarp; n0 < NN; n0 += 4*nwarp) {
    // ---- phase 1: gather 4 nodes x 4 configs into fp16 sy ----
    #pragma unroll
    for (int r = 0; r < 4; r++)
      gather_node(n0 + r, coff, xsrc, syw + r*128, lane, cfg_local);
    __syncwarp();

    int n_lo = n0 + (gid >> 2);
    int n_hi = n_lo + 2;
    int cg   = CH*4 + (gid & 3);

    uint alo[8], ahi[8];       // fp16 stash; later the Wd A-frags
    float ssl = 0.f, ssh = 0.f;

    if (LAYER > 0) {
      const uint* gxu = (const uint*)g_x;
      uint afr[4][4];
      #pragma unroll
      for (int kt = 0; kt < 4; kt++){
        afr[kt][0] = __ldg(gxu + ((size_t)cg*NN + n_lo)*32 + kt*8 + t4);
        afr[kt][1] = __ldg(gxu + ((size_t)cg*NN + n_hi)*32 + kt*8 + t4);
        afr[kt][2] = __ldg(gxu + ((size_t)cg*NN + n_lo)*32 + kt*8 + t4 + 4);
        afr[kt][3] = __ldg(gxu + ((size_t)cg*NN + n_hi)*32 + kt*8 + t4 + 4);
      }
      #pragma unroll
      for (int nt = 0; nt < 8; nt++){
        float2 bpv = __ldg((const float2*)(bp + nt*8 + t4*2));
        float c0 = bpv.x, c1 = bpv.y, c2 = bpv.x, c3 = bpv.y;
        #pragma unroll
        for (int kt = 0; kt < 4; kt++){
          uint bh0 = wph[(nt*8+gid)*32 + kt*8 + t4];
          uint bh1 = wph[(nt*8+gid)*32 + kt*8 + t4 + 4];
          uint bl0 = wpl[(nt*8+gid)*32 + kt*8 + t4];
          uint bl1 = wpl[(nt*8+gid)*32 + kt*8 + t4 + 4];
          mma16816(c0, c1, c2, c3, afr[kt][0], afr[kt][1], afr[kt][2], afr[kt][3], bh0, bh1);
          mma16816(c0, c1, c2, c3, afr[kt][0], afr[kt][1], afr[kt][2], afr[kt][3], bl0, bl1);
        }
        float2 bdv = __ldg((const float2*)(bd + nt*8 + t4*2));
        float2 ylo = __half22float2(syw[(gid>>2)*128     + (gid&3)*32 + nt*4 + t4]);
        float2 yhi = __half22float2(syw[((gid>>2)+2)*128 + (gid&3)*32 + nt*4 + t4]);
        c0 += lrelu(ylo.x + bdv.x);
        c1 += lrelu(ylo.y + bdv.y);
        c2 += lrelu(yhi.x + bdv.x);
        c3 += lrelu(yhi.y + bdv.y);
        ssl += c0*c0 + c1*c1;
        ssh += c2*c2 + c3*c3;
        half2 vlo = __floats2half2_rn(c0, c1);
        half2 vhi = __floats2half2_rn(c2, c3);
        alo[nt] = *(uint*)&vlo;
        ahi[nt] = *(uint*)&vhi;
      }
    } else {
      const float2* xp2 = (const float2*)g_xp;
      #pragma unroll
      for (int nt = 0; nt < 8; nt++){
        float2 lo = __ldg(xp2 + ((size_t)cg*NN + n_lo)*32 + nt*4 + t4);
        float2 hi = __ldg(xp2 + ((size_t)cg*NN + n_hi)*32 + nt*4 + t4);
        float2 bdv = __ldg((const float2*)(bd + nt*8 + t4*2));
        float2 ylo = __half22float2(syw[(gid>>2)*128     + (gid&3)*32 + nt*4 + t4]);
        float2 yhi = __half22float2(syw[((gid>>2)+2)*128 + (gid&3)*32 + nt*4 + t4]);
        float c0 = lo.x + lrelu(ylo.x + bdv.x);
        float c1 = lo.y + lrelu(ylo.y + bdv.y);
        float c2 = hi.x + lrelu(yhi.x + bdv.x);
        float c3 = hi.y + lrelu(yhi.y + bdv.y);
        ssl += c0*c0 + c1*c1;
        ssh += c2*c2 + c3*c3;
        half2 vlo = __floats2half2_rn(c0, c1);
        half2 vhi = __floats2half2_rn(c2, c3);
        alo[nt] = *(uint*)&vlo;
        ahi[nt] = *(uint*)&vhi;
      }
    }

    ssl += __shfl_xor_sync(0xffffffffu, ssl, 1);
    ssl += __shfl_xor_sync(0xffffffffu, ssl, 2);
    ssh += __shfl_xor_sync(0xffffffffu, ssh, 1);
    ssh += __shfl_xor_sync(0xffffffffu, ssh, 2);
    half2 rl2 = __float2half2_rn(rsqrtf(fmaxf(ssl, 1e-12f)));
    half2 rh2 = __float2half2_rn(rsqrtf(fmaxf(ssh, 1e-12f)));

    #pragma unroll
    for (int nt = 0; nt < 8; nt++){
      half2 vlo = __hmul2(*(half2*)&alo[nt], rl2);
      half2 vhi = __hmul2(*(half2*)&ahi[nt], rh2);
      gxo[((size_t)cg*NN + n_lo)*32 + nt*4 + t4] = vlo;
      gxo[((size_t)cg*NN + n_hi)*32 + nt*4 + t4] = vhi;
      alo[nt] = *(uint*)&vlo;
      ahi[nt] = *(uint*)&vhi;
    }

    // ---- Wd MMA: xd_next = x' @ Wd (A frags = stash registers) ----
    if (LAYER < 2) {
      half2* xdo = (half2*)g_xd4[DST];
      #pragma unroll
      for (int nt = 0; nt < 8; nt++){
        float c0 = 0.f, c1 = 0.f, c2 = 0.f, c3 = 0.f;
        #pragma unroll
        for (int kt = 0; kt < 4; kt++){
          uint a0 = alo[2*kt], a1 = ahi[2*kt], a2 = alo[2*kt+1], a3 = ahi[2*kt+1];
          uint bh0 = wdh[(nt*8+gid)*32 + kt*8 + t4];
          uint bh1 = wdh[(nt*8+gid)*32 + kt*8 + t4 + 4];
          uint bl0 = wdl[(nt*8+gid)*32 + kt*8 + t4];
          uint bl1 = wdl[(nt*8+gid)*32 + kt*8 + t4 + 4];
          mma16816(c0, c1, c2, c3, a0, a1, a2, a3, bh0, bh1);
          mma16816(c0, c1, c2, c3, a0, a1, a2, a3, bl0, bl1);
        }
        xdo[(size_t)n_lo*256 + cg*32 + nt*4 + t4] = __floats2half2_rn(c0, c1);
        xdo[(size_t)n_hi*256 + cg*32 + nt*4 + t4] = __floats2half2_rn(c2, c3);
      }
    }
    __syncwarp();
  }
}

// ---------------- pooling (fp16 g_x) ----------------
#define PCHUNK 64
#define NCHUNKS ((NN + PCHUNK - 1) / PCHUNK)
__global__ void k_pool(const int* __restrict__ gid) {
  int gw   = (blockIdx.x*blockDim.x + threadIdx.x) >> 5;
  int lane = threadIdx.x & 31;
  int nw   = (gridDim.x*blockDim.x) >> 5;
  const int TOT = NCHUNKS * CC;
  for (int w = gw; w < TOT; w += nw) {
    int c  = w / NCHUNKS;
    int ch = w - c*NCHUNKS;
    int n0 = ch * PCHUNK;
    int n1 = n0 + PCHUNK; if (n1 > NN) n1 = NN;
    const half2* xs = (const half2*)g_x + ((size_t)c*NN)*32;
    float p0 = 0.f, p1 = 0.f;
    int curg = __ldg(gid + n0);
    for (int n = n0; n < n1; n += 4) {
      int4 g4 = __ldg((const int4*)(gid + n));
      float2 v0 = __half22float2(xs[(size_t)(n  )*32 + lane]);
      float2 v1 = __half22float2(xs[(size_t)(n+1)*32 + lane]);
      float2 v2 = __half22float2(xs[(size_t)(n+2)*32 + lane]);
      float2 v3 = __half22float2(xs[(size_t)(n+3)*32 + lane]);
      int gg[4] = {g4.x, g4.y, g4.z, g4.w};
      float vx[4] = {v0.x, v1.x, v2.x, v3.x};
      float vy[4] = {v0.y, v1.y, v2.y, v3.y};
      #pragma unroll
      for (int k = 0; k < 4; k++) {
        if (gg[k] != curg) {
          atomicAdd(&g_pooled[((size_t)curg*CC + c)*HH + 2*lane    ], p0);
          atomicAdd(&g_pooled[((size_t)curg*CC + c)*HH + 2*lane + 1], p1);
          p0 = 0.f; p1 = 0.f; curg = gg[k];
        }
        p0 += vx[k]; p1 += vy[k];
      }
    }
    atomicAdd(&g_pooled[((size_t)curg*CC + c)*HH + 2*lane    ], p0);
    atomicAdd(&g_pooled[((size_t)curg*CC + c)*HH + 2*lane + 1], p1);
  }
}

// ---------------- final MLP ----------------
__global__ void k_mlp(const float* __restrict__ Wm0, const float* __restrict__ bm0,
                      const float* __restrict__ Wm1, const float* __restrict__ bm1,
                      const float* __restrict__ Wm2, const float* __restrict__ bm2,
                      float* __restrict__ out) {
  __shared__ float s_in[HH], s_h[HH], rr[HH];
  int bc = blockIdx.x;
  int h = threadIdx.x;
  s_in[h] = g_pooled[(size_t)bc*HH + h];
  __syncthreads();
  float a = __ldg(bm0 + h);
  #pragma unroll 8
  for (int d = 0; d < HH; d++) a += s_in[d] * __ldg(Wm0 + d*HH + h);
  a = lrelu(a);
  s_h[h] = a;
  __syncthreads();
  float a2 = __ldg(bm1 + h);
  #pragma unroll 8
  for (int d = 0; d < HH; d++) a2 += s_h[d] * __ldg(Wm1 + d*HH + h);
  a2 = lrelu(a2);
  rr[h] = a2 * __ldg(Wm2 + h);
  __syncthreads();
  if (h < 32) {
    float v = rr[h] + rr[h+32];
    v = warp_sum(v);
    if (h == 0) out[bc] = v + __ldg(bm2);
  }
}

// ---------------- host orchestration ----------------
extern "C" void kernel_launch(void* const* d_in, const int* in_sizes, int n_in,
                              void* d_out, int out_size) {
  (void)in_sizes; (void)n_in; (void)out_size;
  const float* node_feats   = (const float*)d_in[0];
  const float* config_feats = (const float*)d_in[1];
  const int*   op_ids       = (const int*)  d_in[2];
  const int*   src          = (const int*)  d_in[3];
  const int*   dst          = (const int*)  d_in[4];
  const int*   graph_ids    = (const int*)  d_in[5];
  const float* op_emb       = (const float*)d_in[6];
  const float* W_d0 = (const float*)d_in[7];  const float* b_d0 = (const float*)d_in[8];
  const float* W_p0 = (const float*)d_in[9];  const float* b_p0 = (const float*)d_in[10];
  const float* W_d1 = (const float*)d_in[11]; const float* b_d1 = (const float*)d_in[12];
  const float* W_p1 = (const float*)d_in[13]; const float* b_p1 = (const float*)d_in[14];
  const float* W_d2 = (const float*)d_in[15]; const float* b_d2 = (const float*)d_in[16];
  const float* W_p2 = (const float*)d_in[17]; const float* b_p2 = (const float*)d_in[18];
  const float* W_m0 = (const float*)d_in[19]; const float* b_m0 = (const float*)d_in[20];
  const float* W_m1 = (const float*)d_in[21]; const float* b_m1 = (const float*)d_in[22];
  const float* W_m2 = (const float*)d_in[23]; const float* b_m2 = (const float*)d_in[24];
  float* out = (float*)d_out;

  cudaFuncSetAttribute(k_fused<0,0,1,0>, cudaFuncAttributeMaxDynamicSharedMemorySize, FSMEM);
  cudaFuncSetAttribute(k_fused<0,0,1,1>, cudaFuncAttributeMaxDynamicSharedMemorySize, FSMEM);
  cudaFuncSetAttribute(k_fused<1,1,0,0>, cudaFuncAttributeMaxDynamicSharedMemorySize, FSMEM);
  cudaFuncSetAttribute(k_fused<1,1,0,1>, cudaFuncAttributeMaxDynamicSharedMemorySize, FSMEM);
  cudaFuncSetAttribute(k_fused<2,0,0,0>, cudaFuncAttributeMaxDynamicSharedMemorySize, FSMEM);
  cudaFuncSetAttribute(k_fused<2,0,0,1>, cudaFuncAttributeMaxDynamicSharedMemorySize, FSMEM);

  k_zero<<<(NN+255)/256, 256>>>();
  k_layer0<<<1024, 128>>>(node_feats, config_feats, op_ids, op_emb,
                          W_d0, W_p0, b_p0, src, dst);
  k_csr_b<<<148, 1024>>>(src, dst);

  // launch 4 (ncu-captured): fused layer 0, config half 0
  k_fused<0,0,1,0><<<2048, 256, FSMEM>>>(nullptr, nullptr, b_d0, W_d1);
  k_fused<0,0,1,1><<<2048, 256, FSMEM>>>(nullptr, nullptr, b_d0, W_d1);
  k_fused<1,1,0,0><<<2048, 256, FSMEM>>>(W_p1, b_p1, b_d1, W_d2);
  k_fused<1,1,0,1><<<2048, 256, FSMEM>>>(W_p1, b_p1, b_d1, W_d2);
  k_fused<2,0,0,0><<<2048, 256, FSMEM>>>(W_p2, b_p2, b_d2, nullptr);
  k_fused<2,0,0,1><<<2048, 256, FSMEM>>>(W_p2, b_p2, b_d2, nullptr);

  k_pool<<<1024, 256>>>(graph_ids);
  k_mlp<<<BB*CC, HH>>>(W_m0, b_m0, W_m1, b_m1, W_m2, b_m2, out);
}